// round 1
// baseline (speedup 1.0000x reference)
#include <cuda_runtime.h>
#include <math_constants.h>

// Problem constants (match reference)
#define KS     7
#define HALF   3
#define B_DIM  32
#define C_DIM  64
#define L_DIM  4096
#define I_DIM  (L_DIM / 2)          // 2048 outputs per (b,c) row
#define TABLE_N 4189                // max flat index b+c+2i = 31+63+2*2047 = 4188
#define TABLE_PAD 4224

// Scratch: the only dilation values the output actually reads.
__device__ float g_table[TABLE_PAD];

// ---------------------------------------------------------------------------
// Kernel A: compute dilation table for flat indices 0..4188.
// flat k -> (b=0, c' = k>>12, l' = k&4095); dil = max_j f[0,c',l'+j-3] + h[c',j]
// h[c,j] = -(j-3)^2 / (4*t[c]); borders padded with -inf.
// ---------------------------------------------------------------------------
__global__ void pp_table_kernel(const float* __restrict__ f,
                                const float* __restrict__ t) {
    int k = blockIdx.x * blockDim.x + threadIdx.x;
    if (k >= TABLE_N) return;
    int c0 = k >> 12;          // 0 or 1
    int l0 = k & (L_DIM - 1);
    float tc = __ldg(&t[c0]);
    float denom = 4.0f * tc;
    const float* frow = f + (size_t)c0 * L_DIM;   // batch 0

    float m = -CUDART_INF_F;
    #pragma unroll
    for (int j = 0; j < KS; ++j) {
        int z = j - HALF;
        int p = l0 + z;
        float h = -(float)(z * z) / denom;
        if (p >= 0 && p < L_DIM) {
            m = fmaxf(m, __ldg(&frow[p]) + h);
        }
    }
    g_table[k] = m;
}

// ---------------------------------------------------------------------------
// Kernel B: out[b,c,i] = table[b + c + 2*i], float4-vectorized stores.
// Output layout [B=32][C=64][I=2048]; per float4: i = 4*i4 + {0..3}.
// ---------------------------------------------------------------------------
__global__ void pp_gather_kernel(float4* __restrict__ out, int n4) {
    int v = blockIdx.x * blockDim.x + threadIdx.x;
    if (v >= n4) return;
    int i4 = v & (I_DIM / 4 - 1);        // & 511
    int c  = (v >> 9) & (C_DIM - 1);     // & 63
    int b  = v >> 15;
    int base = b + c + 8 * i4;           // table idx for element i = 4*i4
    float4 r;
    r.x = g_table[base];
    r.y = g_table[base + 2];
    r.z = g_table[base + 4];
    r.w = g_table[base + 6];
    out[v] = r;
}

extern "C" void kernel_launch(void* const* d_in, const int* in_sizes, int n_in,
                              void* d_out, int out_size) {
    const float* f = (const float*)d_in[0];   // [32, 64, 4096] float32
    const float* t = (const float*)d_in[1];   // [64] float32
    float4* out = (float4*)d_out;             // [32, 64, 2048] float32

    // Kernel A: 4189 table entries
    {
        int threads = 256;
        int blocks = (TABLE_N + threads - 1) / threads;   // 17
        pp_table_kernel<<<blocks, threads>>>(f, t);
    }
    // Kernel B: out_size/4 float4 stores
    {
        int n4 = out_size / 4;                 // 1,048,576
        int threads = 256;
        int blocks = (n4 + threads - 1) / threads;  // 4096
        pp_gather_kernel<<<blocks, threads>>>(out, n4);
    }
}

// round 2
// speedup vs baseline: 1.1875x; 1.1875x over previous
#include <cuda_runtime.h>
#include <math_constants.h>

// Problem constants
#define KS       7
#define HALF     3
#define B_DIM    32
#define C_DIM    64
#define L_DIM    4096
#define I_DIM    (L_DIM / 2)     // 2048 outputs per (b,c) row
#define TABLE_N  4189            // max flat index b+c+2i = 31+63+2*2047 = 4188

// Deinterleaved dilation tables:
//   g_tabE[k] = dil(2k)   (even flat indices, k <= 2094)
//   g_tabO[k] = dil(2k+1) (odd  flat indices, k <= 2093)
__device__ float g_tabE[2112];
__device__ float g_tabO[2112];

// ---------------------------------------------------------------------------
// Kernel A: dilation table for flat indices 0..4188, written deinterleaved.
// flat k -> (b=0, c'=k>>12, l'=k&4095); dil = max_j f[0,c',l'+j-3] + h[c',j]
// h[c,j] = -(j-3)^2 / (4*t[c]); -inf padding at l' borders.
// ---------------------------------------------------------------------------
__global__ void pp_table_kernel(const float* __restrict__ f,
                                const float* __restrict__ t) {
    int k = blockIdx.x * blockDim.x + threadIdx.x;
    if (k >= TABLE_N) return;
    int c0 = k >> 12;               // 0 or 1
    int l0 = k & (L_DIM - 1);
    float denom = 4.0f * __ldg(&t[c0]);
    const float* frow = f + c0 * L_DIM;   // batch 0

    float m = -CUDART_INF_F;
    #pragma unroll
    for (int j = 0; j < KS; ++j) {
        int z = j - HALF;
        int p = l0 + z;
        float h = -(float)(z * z) / denom;
        if (p >= 0 && p < L_DIM)
            m = fmaxf(m, __ldg(&frow[p]) + h);
    }
    if (k & 1) g_tabO[k >> 1] = m;
    else       g_tabE[k >> 1] = m;
}

// ---------------------------------------------------------------------------
// Kernel B: out[b,c,i] = table[b + c + 2*i].
// Per row s=b+c has fixed parity, so elements are CONTIGUOUS in the parity-
// selected table: element i = tabP[(s>>1) + i]. Each 256-thread block owns
// half a row (1024 floats): stage the contiguous slice into smem (coalesced,
// absorbs misalignment), then one conflict-free LDS.128 + STG.128 per thread.
// ---------------------------------------------------------------------------
__global__ void __launch_bounds__(256) pp_gather_kernel(float4* __restrict__ out) {
    __shared__ float sm[1024];
    int tid = threadIdx.x;
    int row = blockIdx.x >> 1;                 // (b,c) row id, 2 blocks/row
    int s   = (row >> 6) + (row & (C_DIM - 1));  // b + c
    const float* __restrict__ tab = (s & 1) ? g_tabO : g_tabE;
    int j0    = (blockIdx.x & 1) << 8;         // float4 offset within row (0 or 256)
    int base0 = (s >> 1) + (j0 << 2);          // element offset in parity table

    // Stage 1024 contiguous floats (coalesced scalar loads, L1-hot table)
    #pragma unroll
    for (int x = tid; x < 1024; x += 256)
        sm[x] = tab[base0 + x];
    __syncthreads();

    // Conflict-free, 16B-aligned vector read + vector store
    float4 r = *reinterpret_cast<const float4*>(&sm[tid << 2]);
    out[blockIdx.x * 256 + tid] = r;
}

extern "C" void kernel_launch(void* const* d_in, const int* in_sizes, int n_in,
                              void* d_out, int out_size) {
    const float* f = (const float*)d_in[0];   // [32, 64, 4096] float32
    const float* t = (const float*)d_in[1];   // [64] float32
    float4* out = (float4*)d_out;             // [32, 64, 2048] float32

    // Kernel A: 4189 table entries, deinterleaved
    {
        int threads = 256;
        int blocks = (TABLE_N + threads - 1) / threads;   // 17
        pp_table_kernel<<<blocks, threads>>>(f, t);
    }
    // Kernel B: one float4 per thread, half-row per block
    {
        int n4 = out_size / 4;                  // 1,048,576 float4
        int blocks = n4 / 256;                  // 4096
        pp_gather_kernel<<<blocks, 256>>>(out);
    }
}

// round 3
// speedup vs baseline: 1.2277x; 1.0338x over previous
#include <cuda_runtime.h>
#include <math_constants.h>

// Problem constants
#define KS       7
#define HALF     3
#define B_DIM    32
#define C_DIM    64
#define L_DIM    4096
#define I_DIM    (L_DIM / 2)
#define TABLE_N  4189            // max flat index b+c+2i = 31+63+2*2047 = 4188

// Alignment-replicated, parity-deinterleaved dilation tables.
// tabP[m] = dil(2m + p).   g_tabA[p][a][e] (as floats) = tabP[4e + a' ...]:
// concretely float view: g_tabA[p][a][m] = tabP[m + a], so an element read
// tabP[(s>>1) + i] with (s>>1) = 4q + a becomes an ALIGNED float4 load
// g_tabA[p][a][q + i/4] when i % 4 == 0.
__device__ float4 g_tabA[2][4][544];   // 544*4 = 2176 floats per copy

// ---------------------------------------------------------------------------
// Kernel A: dilation for flat indices 0..4188, written to all 8 copies.
// flat k -> (b=0, c'=k>>12, l'=k&4095); dil = max_j f[0,c',l'+j-3] + h[c',j]
// h[c,j] = -(j-3)^2 / (4*t[c]); -inf padding at l' borders.
// ---------------------------------------------------------------------------
__global__ void pp_table_kernel(const float* __restrict__ f,
                                const float* __restrict__ t) {
    int k = blockIdx.x * blockDim.x + threadIdx.x;
    if (k >= TABLE_N) return;
    int c0 = k >> 12;               // 0 or 1
    int l0 = k & (L_DIM - 1);
    float denom = 4.0f * __ldg(&t[c0]);
    const float* frow = f + c0 * L_DIM;   // batch 0

    float m = -CUDART_INF_F;
    #pragma unroll
    for (int j = 0; j < KS; ++j) {
        int z = j - HALF;
        int p = l0 + z;
        float h = -(float)(z * z) / denom;
        if (p >= 0 && p < L_DIM)
            m = fmaxf(m, __ldg(&frow[p]) + h);
    }

    int par = k & 1;
    int idx = k >> 1;               // index within parity table, <= 2094
    #pragma unroll
    for (int a = 0; a < 4; ++a) {
        if (idx >= a)
            reinterpret_cast<float*>(g_tabA[par][a])[idx - a] = m;
    }
}

// ---------------------------------------------------------------------------
// Kernel B: out[b,c,i] = dil(s + 2i), s = b + c.
// One aligned LDG.128 + one STG.128 per thread. Tables (70 KB) are L1-hot.
// ---------------------------------------------------------------------------
__global__ void __launch_bounds__(256) pp_gather_kernel(float4* __restrict__ out) {
    int v   = blockIdx.x * 256 + threadIdx.x;   // global float4 id
    int i4  = v & (I_DIM / 4 - 1);              // & 511
    int row = v >> 9;
    int s   = (row >> 6) + (row & (C_DIM - 1)); // b + c
    int hs  = s >> 1;
    const float4* __restrict__ tab = g_tabA[s & 1][hs & 3];
    out[v] = __ldg(&tab[(hs >> 2) + i4]);
}

extern "C" void kernel_launch(void* const* d_in, const int* in_sizes, int n_in,
                              void* d_out, int out_size) {
    const float* f = (const float*)d_in[0];   // [32, 64, 4096] float32
    const float* t = (const float*)d_in[1];   // [64] float32
    float4* out = (float4*)d_out;             // [32, 64, 2048] float32

    // Kernel A: 4189 table entries, 8 shifted copies
    {
        int threads = 256;
        int blocks = (TABLE_N + threads - 1) / threads;   // 17
        pp_table_kernel<<<blocks, threads>>>(f, t);
    }
    // Kernel B: one float4 per thread
    {
        int n4 = out_size / 4;                  // 1,048,576 float4
        pp_gather_kernel<<<n4 / 256, 256>>>(out);
    }
}